// round 5
// baseline (speedup 1.0000x reference)
#include <cuda_runtime.h>
#include <cuda_bf16.h>
#include <cstdint>

// Problem dims (fixed by the dataset)
#define T_STEPS 128
#define BATCH   128
#define D_IN    1024
#define D_OUT   1024
#define M_TOT   (T_STEPS * BATCH)   // 16384
#define BD      (BATCH * D_OUT)     // 131072

// GEMM tiling
#define BM 128
#define BN 128
#define BK 16
#define TM 8
#define TN 8
#define NTHREADS 256

// Split-K emulation: 2 contiguous chunks of 512, combined with one rounded add.
#define NSPLIT 2
#define KCHUNK (D_IN / NSPLIT)   // 512

// Scratch for X = A @ W + b  (64 MB) — __device__ global, no allocation.
__device__ float g_X[(size_t)M_TOT * D_OUT];

// ---------------------------------------------------------------------------
// Kernel 1: X[16384,1024] = A[16384,1024] @ W[1024,1024] + b
// Split-K=2 ordering: per output element,
//   c_s = sum_{k in chunk s, ascending} fmaf(a_k, w_k, c_s)   (s = 0,1)
//   x   = c0 + c1                      (one separately-rounded add)
//   X   = x + bias                     (one more rounded add)
// ---------------------------------------------------------------------------
__global__ __launch_bounds__(NTHREADS)
void sgemm_bias_splitk_kernel(const float* __restrict__ A,
                              const float* __restrict__ W,
                              const float* __restrict__ bias)
{
    __shared__ float As[BK][BM];   // transposed A tile
    __shared__ float Ws[BK][BN];

    const int bx = blockIdx.x;     // N tile index (0..7)
    const int by = blockIdx.y;     // M tile index (0..127)
    const int tid = threadIdx.x;
    const int tx = tid % 16;       // 0..15 -> N sub
    const int ty = tid / 16;       // 0..15 -> M sub

    const float* Ablk = A + (size_t)by * BM * D_IN;

    // A tile loads: 128 rows x 16 cols = 512 float4; 2 per thread
    const int a_row  = tid >> 2;          // 0..63 (+64)
    const int a_col4 = tid & 3;           // float4 index within 16 cols
    // W tile loads: 16 rows x 128 cols = 512 float4; 2 per thread
    const int w_row  = tid >> 5;          // 0..7 (+8)
    const int w_col4 = tid & 31;          // float4 index within 128 cols

    float tot[TM][TN];             // combined split partials
    float acc[TM][TN];             // current chunk accumulator

    for (int c = 0; c < NSPLIT; c++) {
        // zero chunk accumulator
        #pragma unroll
        for (int i = 0; i < TM; i++)
            #pragma unroll
            for (int j = 0; j < TN; j++)
                acc[i][j] = 0.0f;

        const int kbase = c * KCHUNK;
        for (int k0 = kbase; k0 < kbase + KCHUNK; k0 += BK) {
            // Load A tile (transpose into As[k][m])
            #pragma unroll
            for (int it = 0; it < 2; it++) {
                int r = a_row + it * 64;
                float4 v = *reinterpret_cast<const float4*>(
                    Ablk + (size_t)r * D_IN + k0 + a_col4 * 4);
                As[a_col4 * 4 + 0][r] = v.x;
                As[a_col4 * 4 + 1][r] = v.y;
                As[a_col4 * 4 + 2][r] = v.z;
                As[a_col4 * 4 + 3][r] = v.w;
            }
            // Load W tile
            #pragma unroll
            for (int it = 0; it < 2; it++) {
                int r = w_row + it * 8;
                *reinterpret_cast<float4*>(&Ws[r][w_col4 * 4]) =
                    *reinterpret_cast<const float4*>(
                        W + (size_t)(k0 + r) * D_OUT + (size_t)bx * BN + w_col4 * 4);
            }
            __syncthreads();

            #pragma unroll
            for (int k = 0; k < BK; k++) {
                float a[TM], w[TN];
                #pragma unroll
                for (int i = 0; i < TM; i++) a[i] = As[k][ty * TM + i];
                #pragma unroll
                for (int j = 0; j < TN; j++) w[j] = Ws[k][tx * TN + j];
                #pragma unroll
                for (int i = 0; i < TM; i++)
                    #pragma unroll
                    for (int j = 0; j < TN; j++)
                        acc[i][j] = fmaf(a[i], w[j], acc[i][j]);
            }
            __syncthreads();
        }

        // Fold chunk into running total with a single rounded add per chunk
        if (c == 0) {
            #pragma unroll
            for (int i = 0; i < TM; i++)
                #pragma unroll
                for (int j = 0; j < TN; j++)
                    tot[i][j] = acc[i][j];
        } else {
            #pragma unroll
            for (int i = 0; i < TM; i++)
                #pragma unroll
                for (int j = 0; j < TN; j++)
                    tot[i][j] = __fadd_rn(tot[i][j], acc[i][j]);
        }
    }

    // Epilogue: add bias (single separately-rounded add), store float4
    #pragma unroll
    for (int i = 0; i < TM; i++) {
        size_t row = (size_t)by * BM + ty * TM + i;
        size_t col = (size_t)bx * BN + tx * TN;
        float* dst = g_X + row * D_OUT + col;
        #pragma unroll
        for (int j4 = 0; j4 < TN / 4; j4++) {
            float4 v;
            v.x = __fadd_rn(tot[i][j4 * 4 + 0], bias[col + j4 * 4 + 0]);
            v.y = __fadd_rn(tot[i][j4 * 4 + 1], bias[col + j4 * 4 + 1]);
            v.z = __fadd_rn(tot[i][j4 * 4 + 2], bias[col + j4 * 4 + 2]);
            v.w = __fadd_rn(tot[i][j4 * 4 + 3], bias[col + j4 * 4 + 3]);
            *reinterpret_cast<float4*>(dst + j4 * 4) = v;
        }
    }
}

// ---------------------------------------------------------------------------
// Kernel 2: LIF scan over T. One thread per (b, d) lane.
//   u = add(mul(0.75, u), x); v = sub(u, 1); s = (v >= 0); u = sub(u, s).
// (Proven insensitive to fma contraction in R1 vs R3.)
// ---------------------------------------------------------------------------
__global__ __launch_bounds__(256)
void lif_scan_kernel(float* __restrict__ out)
{
    int idx = blockIdx.x * blockDim.x + threadIdx.x;   // 0 .. BD-1
    float u = 0.0f;
    #pragma unroll 8
    for (int t = 0; t < T_STEPS; t++) {
        float x = g_X[(size_t)t * BD + idx];
        u = __fadd_rn(__fmul_rn(0.75f, u), x);
        float v = __fsub_rn(u, 1.0f);
        float s = (v >= 0.0f) ? 1.0f : 0.0f;
        out[(size_t)t * BD + idx] = s;
        u = __fsub_rn(u, s);
    }
}

// ---------------------------------------------------------------------------
extern "C" void kernel_launch(void* const* d_in, const int* in_sizes, int n_in,
                              void* d_out, int out_size)
{
    const float* inputs = (const float*)d_in[0];   // [T, B, D_in]
    const float* W      = (const float*)d_in[1];   // [D_in, D_out]
    const float* bias   = (const float*)d_in[2];   // [D_out]
    float* out          = (float*)d_out;           // [T, B, D_out]

    dim3 gemm_grid(D_OUT / BN, M_TOT / BM);        // (8, 128)
    sgemm_bias_splitk_kernel<<<gemm_grid, NTHREADS>>>(inputs, W, bias);

    lif_scan_kernel<<<BD / 256, 256>>>(out);
}

// round 6
// speedup vs baseline: 1.1335x; 1.1335x over previous
#include <cuda_runtime.h>
#include <cuda_bf16.h>
#include <cstdint>

// Problem dims (fixed by the dataset)
#define T_STEPS 128
#define BATCH   128
#define D_IN    1024
#define D_OUT   1024
#define M_TOT   (T_STEPS * BATCH)   // 16384
#define BD      (BATCH * D_OUT)     // 131072

// GEMM tiling
#define BM 128
#define BN 128
#define BK 16
#define TM 8
#define NTHREADS 256
#define NITER   (D_IN / BK)     // 64
#define FOLD_IT 32              // iteration where K=512 chunk boundary falls

// Scratch for X = A @ W + b  (64 MB) — __device__ global, no allocation.
__device__ float g_X[(size_t)M_TOT * D_OUT];

typedef unsigned long long ull;

// Packed f32x2: two independent IEEE-rn fp32 ops per instruction.
// Per-lane results are bit-identical to scalar FFMA / FADD.rn.
__device__ __forceinline__ ull fma2(ull a, ull b, ull c) {
    ull d;
    asm("fma.rn.f32x2 %0, %1, %2, %3;" : "=l"(d) : "l"(a), "l"(b), "l"(c));
    return d;
}
__device__ __forceinline__ ull add2(ull a, ull b) {
    ull d;
    asm("add.rn.f32x2 %0, %1, %2;" : "=l"(d) : "l"(a), "l"(b));
    return d;
}
__device__ __forceinline__ float2 unpack2(ull v) {
    float2 f;
    asm("mov.b64 {%0, %1}, %2;" : "=f"(f.x), "=f"(f.y) : "l"(v));
    return f;
}

// ---------------------------------------------------------------------------
// Kernel 1: X[16384,1024] = A[16384,1024] @ W[1024,1024] + b
// Bit-exact split-K=2 ordering (PROVEN in round 5):
//   c0 = serial ascending FFMA over k=0..511
//   c1 = serial ascending FFMA over k=512..1023
//   X  = ((c0 + c1) + bias), each add separately rounded.
// Implemented with packed fma.rn.f32x2 (2 MACs/instr, per-lane identical
// rounding) + double-buffered smem pipeline (1 syncthreads per K-tile).
// A tile stored DUPLICATED ({a,a} pairs) so the packed broadcast operand
// comes straight from an LDS (uniform address across tx -> pure broadcast).
// ---------------------------------------------------------------------------
__global__ __launch_bounds__(NTHREADS, 1)
void sgemm_bias_splitk2_f32x2_kernel(const float* __restrict__ A,
                                     const float* __restrict__ W,
                                     const float* __restrict__ bias)
{
    __shared__ float As2[2][BK][2 * BM];   // duplicated A: 2 * 16KB
    __shared__ float Ws [2][BK][BN];       // 2 * 8KB

    const int bx = blockIdx.x;             // N tile (0..7)
    const int by = blockIdx.y;             // M tile (0..127)
    const int tid = threadIdx.x;
    const int tx = tid & 15;               // n sub
    const int ty = tid >> 4;               // m sub

    const float* Ablk = A + (size_t)by * BM * D_IN;

    // A tile: 128 rows x 16 cols = 512 float4; 2 per thread
    const int a_row  = tid >> 2;           // 0..63 (+64)
    const int a_col4 = tid & 3;
    // W tile: 16 rows x 128 cols = 512 float4; 2 per thread
    const int w_row  = tid >> 5;           // 0..7 (+8)
    const int w_col4 = tid & 31;

    float4 areg[2], wreg[2];

    auto load_tile = [&](int k0) {
        #pragma unroll
        for (int i = 0; i < 2; i++) {
            int r = a_row + i * 64;
            areg[i] = *reinterpret_cast<const float4*>(
                Ablk + (size_t)r * D_IN + k0 + a_col4 * 4);
        }
        #pragma unroll
        for (int i = 0; i < 2; i++) {
            int r = w_row + i * 8;
            wreg[i] = *reinterpret_cast<const float4*>(
                W + (size_t)(k0 + r) * D_OUT + (size_t)bx * BN + w_col4 * 4);
        }
    };
    auto store_tile = [&](int s) {
        #pragma unroll
        for (int i = 0; i < 2; i++) {
            int r = a_row + i * 64;
            // transpose + duplicate: As2[k][2m] = As2[k][2m+1] = A[m][k]
            *reinterpret_cast<float2*>(&As2[s][a_col4 * 4 + 0][2 * r]) =
                make_float2(areg[i].x, areg[i].x);
            *reinterpret_cast<float2*>(&As2[s][a_col4 * 4 + 1][2 * r]) =
                make_float2(areg[i].y, areg[i].y);
            *reinterpret_cast<float2*>(&As2[s][a_col4 * 4 + 2][2 * r]) =
                make_float2(areg[i].z, areg[i].z);
            *reinterpret_cast<float2*>(&As2[s][a_col4 * 4 + 3][2 * r]) =
                make_float2(areg[i].w, areg[i].w);
        }
        #pragma unroll
        for (int i = 0; i < 2; i++) {
            int r = w_row + i * 8;
            *reinterpret_cast<float4*>(&Ws[s][r][w_col4 * 4]) = wreg[i];
        }
    };

    ull acc2[TM][4];   // lanes: n = tx*8 + 2j (lo), +1 (hi); m = ty*8 + i
    ull tot2[TM][4];
    #pragma unroll
    for (int i = 0; i < TM; i++)
        #pragma unroll
        for (int j = 0; j < 4; j++)
            acc2[i][j] = 0ULL;

    load_tile(0);
    store_tile(0);
    __syncthreads();
    int cur = 0;

    for (int it = 0; it < NITER; ++it) {
        if (it + 1 < NITER) load_tile((it + 1) * BK);

        if (it == FOLD_IT) {
            // chunk boundary: save c0, restart accumulator for c1
            #pragma unroll
            for (int i = 0; i < TM; i++)
                #pragma unroll
                for (int j = 0; j < 4; j++) {
                    tot2[i][j] = acc2[i][j];
                    acc2[i][j] = 0ULL;
                }
        }

        // compute on smem[cur]
        #pragma unroll
        for (int k = 0; k < BK; k++) {
            const float* asrc = &As2[cur][k][2 * (ty * TM)];  // 8 dup pairs
            const float* wsrc = &Ws[cur][k][tx * 8];          // 4 n-pairs
            ull a2[TM], w2[4];
            #pragma unroll
            for (int i = 0; i < TM; i++)
                a2[i] = *reinterpret_cast<const ull*>(asrc + 2 * i);
            #pragma unroll
            for (int j = 0; j < 4; j++)
                w2[j] = *reinterpret_cast<const ull*>(wsrc + 2 * j);
            #pragma unroll
            for (int i = 0; i < TM; i++)
                #pragma unroll
                for (int j = 0; j < 4; j++)
                    acc2[i][j] = fma2(a2[i], w2[j], acc2[i][j]);
        }

        if (it + 1 < NITER) {
            store_tile(cur ^ 1);
            __syncthreads();
            cur ^= 1;
        }
    }

    // final combine: tot = c0 + c1 (one rn add per lane)
    #pragma unroll
    for (int i = 0; i < TM; i++)
        #pragma unroll
        for (int j = 0; j < 4; j++)
            tot2[i][j] = add2(tot2[i][j], acc2[i][j]);

    // Epilogue: + bias (one rn add), store float4
    #pragma unroll
    for (int i = 0; i < TM; i++) {
        size_t row = (size_t)by * BM + ty * TM + i;
        size_t col = (size_t)bx * BN + tx * 8;
        float* dst = g_X + row * D_OUT + col;
        float2 p0 = unpack2(tot2[i][0]);
        float2 p1 = unpack2(tot2[i][1]);
        float2 p2 = unpack2(tot2[i][2]);
        float2 p3 = unpack2(tot2[i][3]);
        float4 v0, v1;
        v0.x = __fadd_rn(p0.x, bias[col + 0]);
        v0.y = __fadd_rn(p0.y, bias[col + 1]);
        v0.z = __fadd_rn(p1.x, bias[col + 2]);
        v0.w = __fadd_rn(p1.y, bias[col + 3]);
        v1.x = __fadd_rn(p2.x, bias[col + 4]);
        v1.y = __fadd_rn(p2.y, bias[col + 5]);
        v1.z = __fadd_rn(p3.x, bias[col + 6]);
        v1.w = __fadd_rn(p3.y, bias[col + 7]);
        *reinterpret_cast<float4*>(dst + 0) = v0;
        *reinterpret_cast<float4*>(dst + 4) = v1;
    }
}

// ---------------------------------------------------------------------------
// Kernel 2: LIF scan over T. One thread per (b, d) lane. (Proven bit-exact.)
// ---------------------------------------------------------------------------
__global__ __launch_bounds__(256)
void lif_scan_kernel(float* __restrict__ out)
{
    int idx = blockIdx.x * blockDim.x + threadIdx.x;   // 0 .. BD-1
    float u = 0.0f;
    #pragma unroll 8
    for (int t = 0; t < T_STEPS; t++) {
        float x = g_X[(size_t)t * BD + idx];
        u = __fadd_rn(__fmul_rn(0.75f, u), x);
        float v = __fsub_rn(u, 1.0f);
        float s = (v >= 0.0f) ? 1.0f : 0.0f;
        out[(size_t)t * BD + idx] = s;
        u = __fsub_rn(u, s);
    }
}

// ---------------------------------------------------------------------------
extern "C" void kernel_launch(void* const* d_in, const int* in_sizes, int n_in,
                              void* d_out, int out_size)
{
    const float* inputs = (const float*)d_in[0];   // [T, B, D_in]
    const float* W      = (const float*)d_in[1];   // [D_in, D_out]
    const float* bias   = (const float*)d_in[2];   // [D_out]
    float* out          = (float*)d_out;           // [T, B, D_out]

    dim3 gemm_grid(D_OUT / BN, M_TOT / BM);        // (8, 128)
    sgemm_bias_splitk2_f32x2_kernel<<<gemm_grid, NTHREADS>>>(inputs, W, bias);

    lif_scan_kernel<<<BD / 256, 256>>>(out);
}